// round 1
// baseline (speedup 1.0000x reference)
#include <cuda_runtime.h>

// Per-edge dot product: out[e] = dot(h[src[e]], h[dst[e]])
// h: [N_NODES, 128] fp32, src/dst: [E] int32, out: [E] fp32.
// One warp per edge: lane l loads float4 #l of each 128-float row
// (32 lanes * 4 floats = 128), accumulates 4 FMAs, warp butterfly reduce.

#define D_FEAT 128
#define VEC_PER_ROW (D_FEAT / 4)   // 32 float4 per row -> exactly one warp

__global__ void __launch_bounds__(256)
edge_dot_kernel(const float* __restrict__ h,
                const int* __restrict__ src,
                const int* __restrict__ dst,
                float* __restrict__ out,
                int n_edges)
{
    const int warps_per_block = blockDim.x >> 5;
    const int edge = blockIdx.x * warps_per_block + (threadIdx.x >> 5);
    const int lane = threadIdx.x & 31;
    if (edge >= n_edges) return;

    // Broadcast index loads (all 32 lanes read the same word -> 1 sector)
    const int s = src[edge];
    const int d = dst[edge];

    const float4* __restrict__ hs =
        reinterpret_cast<const float4*>(h + (size_t)s * D_FEAT);
    const float4* __restrict__ hd =
        reinterpret_cast<const float4*>(h + (size_t)d * D_FEAT);

    // Two independent 16B loads per lane -> coalesced 512B per row per warp.
    const float4 a = __ldg(&hs[lane]);
    const float4 b = __ldg(&hd[lane]);

    float sum = a.x * b.x + a.y * b.y + a.z * b.z + a.w * b.w;

    // Warp reduction (butterfly)
    #pragma unroll
    for (int off = 16; off > 0; off >>= 1)
        sum += __shfl_xor_sync(0xFFFFFFFFu, sum, off);

    if (lane == 0)
        out[edge] = sum;
}

extern "C" void kernel_launch(void* const* d_in, const int* in_sizes, int n_in,
                              void* d_out, int out_size)
{
    const float* h   = (const float*)d_in[0];
    const int*   src = (const int*)d_in[1];
    const int*   dst = (const int*)d_in[2];
    float*       out = (float*)d_out;

    const int n_edges = in_sizes[1];   // element count of src

    const int threads = 256;
    const int warps_per_block = threads / 32;
    const int blocks = (n_edges + warps_per_block - 1) / warps_per_block;

    edge_dot_kernel<<<blocks, threads>>>(h, src, dst, out, n_edges);
}

// round 2
// speedup vs baseline: 2.0704x; 2.0704x over previous
#include <cuda_runtime.h>

// Per-edge dot product: out[e] = dot(h[src[e]], h[dst[e]])
// h: [100000, 128] fp32, src/dst: [E] int32, out: [E] fp32.
//
// 8 lanes per edge, 4 edges per warp. Each lane loads 4 float4 from the src
// row and 4 from the dst row (8 independent LDG.128 in flight -> MLP=8).
// Interleaved mapping (float4 index = sub + 8*j) so each LDG per 8-lane
// group covers one dense 128B line (minimal L1 wavefronts).
// Reduction: 3 butterfly shuffles within the 8-lane group.

#define D_FEAT 128
#define F4_PER_ROW 32   // 128 floats = 32 float4

__global__ void __launch_bounds__(256)
edge_dot_kernel(const float4* __restrict__ h4,
                const int* __restrict__ src,
                const int* __restrict__ dst,
                float* __restrict__ out,
                int n_edges)
{
    const int lane  = threadIdx.x & 31;
    const int group = lane >> 3;       // 0..3 : which edge within the warp
    const int sub   = lane & 7;        // 0..7 : lane within the edge group

    const int warp_global = (blockIdx.x * blockDim.x + threadIdx.x) >> 5;
    const int edge = warp_global * 4 + group;

    // Clamp (no early return: keep all lanes active for shuffles)
    const bool valid = (edge < n_edges);
    const int e = valid ? edge : (n_edges - 1);

    const int s = __ldg(&src[e]);
    const int d = __ldg(&dst[e]);

    const float4* __restrict__ hs = h4 + (size_t)s * F4_PER_ROW;
    const float4* __restrict__ hd = h4 + (size_t)d * F4_PER_ROW;

    // 8 independent loads, front-batched by the compiler.
    float4 a0 = __ldg(&hs[sub +  0]);
    float4 a1 = __ldg(&hs[sub +  8]);
    float4 a2 = __ldg(&hs[sub + 16]);
    float4 a3 = __ldg(&hs[sub + 24]);
    float4 b0 = __ldg(&hd[sub +  0]);
    float4 b1 = __ldg(&hd[sub +  8]);
    float4 b2 = __ldg(&hd[sub + 16]);
    float4 b3 = __ldg(&hd[sub + 24]);

    float sum;
    sum  = a0.x * b0.x;
    sum  = fmaf(a0.y, b0.y, sum);
    sum  = fmaf(a0.z, b0.z, sum);
    sum  = fmaf(a0.w, b0.w, sum);
    sum  = fmaf(a1.x, b1.x, sum);
    sum  = fmaf(a1.y, b1.y, sum);
    sum  = fmaf(a1.z, b1.z, sum);
    sum  = fmaf(a1.w, b1.w, sum);
    sum  = fmaf(a2.x, b2.x, sum);
    sum  = fmaf(a2.y, b2.y, sum);
    sum  = fmaf(a2.z, b2.z, sum);
    sum  = fmaf(a2.w, b2.w, sum);
    sum  = fmaf(a3.x, b3.x, sum);
    sum  = fmaf(a3.y, b3.y, sum);
    sum  = fmaf(a3.z, b3.z, sum);
    sum  = fmaf(a3.w, b3.w, sum);

    // Reduce within 8-lane group (xor stays inside the aligned segment)
    sum += __shfl_xor_sync(0xFFFFFFFFu, sum, 4);
    sum += __shfl_xor_sync(0xFFFFFFFFu, sum, 2);
    sum += __shfl_xor_sync(0xFFFFFFFFu, sum, 1);

    if (valid && sub == 0)
        out[edge] = sum;
}

extern "C" void kernel_launch(void* const* d_in, const int* in_sizes, int n_in,
                              void* d_out, int out_size)
{
    const float4* h4  = (const float4*)d_in[0];
    const int*    src = (const int*)d_in[1];
    const int*    dst = (const int*)d_in[2];
    float*        out = (float*)d_out;

    const int n_edges = in_sizes[1];          // element count of src

    const int threads = 256;
    const int edges_per_block = (threads / 32) * 4;  // 32 edges per block
    const int blocks = (n_edges + edges_per_block - 1) / edges_per_block;

    edge_dot_kernel<<<blocks, threads>>>(h4, src, dst, out, n_edges);
}